// round 2
// baseline (speedup 1.0000x reference)
#include <cuda_runtime.h>
#include <cstdint>

#define N_NODES  100000
#define N_EDGES  1600000
#define N_GRAPHS 50
#define FDIM     128

// Scratch: edge aggregations (2 x 51.2MB, L2-resident working set) + projected globals
__device__ __align__(128) float g_agg[2][(size_t)N_NODES * FDIM];
__device__ __align__(128) float g_gproj[N_GRAPHS * FDIM];

// ---------------------------------------------------------------------------
// helpers
// ---------------------------------------------------------------------------
__device__ __forceinline__ unsigned smem_u32(const void* p) {
    unsigned a;
    asm("{ .reg .u64 t; cvta.to.shared.u64 t, %1; cvt.u32.u64 %0, t; }"
        : "=r"(a) : "l"(p));
    return a;
}
__device__ __forceinline__ unsigned long long pk(float lo, float hi) {
    unsigned long long r;
    asm("mov.b64 %0, {%1, %2};" : "=l"(r) : "f"(lo), "f"(hi));
    return r;
}
__device__ __forceinline__ void fma2(unsigned long long& d,
                                     unsigned long long a,
                                     unsigned long long b) {
    asm("fma.rn.f32x2 %0, %1, %2, %0;" : "+l"(d) : "l"(a), "l"(b));
}

// ---------------------------------------------------------------------------
// Zero the aggregation buffers
// ---------------------------------------------------------------------------
__global__ void zero_kernel() {
    size_t n = ((size_t)2 * N_NODES * FDIM) / 4;
    float4* p = (float4*)g_agg;
    float4 z = make_float4(0.f, 0.f, 0.f, 0.f);
    for (size_t i = (size_t)blockIdx.x * blockDim.x + threadIdx.x; i < n;
         i += (size_t)gridDim.x * blockDim.x)
        p[i] = z;
}

// ---------------------------------------------------------------------------
// Project globals: g_gproj[g][j] = dot(G[g], Wg[j]) + bias[j]
// ---------------------------------------------------------------------------
__global__ void gproj_kernel(const float* __restrict__ gf,
                             const float* __restrict__ Wg,
                             const float* __restrict__ bias) {
    __shared__ float s[FDIM];
    int g = blockIdx.x, j = threadIdx.x;
    s[j] = gf[g * FDIM + j];
    __syncthreads();
    const float4* wrow = (const float4*)(Wg + (size_t)j * FDIM);
    float acc = 0.f;
#pragma unroll
    for (int k = 0; k < FDIM / 4; k++) {
        float4 w = wrow[k];
        const float4 a = *(const float4*)&s[k * 4];
        acc += a.x * w.x + a.y * w.y + a.z * w.z + a.w * w.w;
    }
    g_gproj[g * FDIM + j] = acc + bias[j];
}

// ---------------------------------------------------------------------------
// Scatter via TMA bulk reduce: stream 32-edge chunks (16KB) into SMEM with
// cp.async.bulk (double-buffered, mbarrier), then each lane fires two
// cp.reduce.async.bulk .add.f32 (512B each) at the recv/send aggregation rows.
// Full 32B L2 sectors per op instead of half-wasted red.v4 lane-ops.
// ---------------------------------------------------------------------------
#define EB 32
#define CHUNK_BYTES (EB * FDIM * 4)   // 16384

__global__ __launch_bounds__(32) void scatter_kernel(
    const float* __restrict__ ef,
    const int* __restrict__ recv,
    const int* __restrict__ send,
    int n_chunks) {
    __shared__ __align__(128) float buf[2][EB * FDIM];
    __shared__ __align__(16) unsigned long long mbar[2];
    const int tid = threadIdx.x;
    const unsigned sbuf = smem_u32(buf);
    const unsigned smb[2] = {smem_u32(&mbar[0]), smem_u32(&mbar[1])};

    if (tid == 0) {
        asm volatile("mbarrier.init.shared.b64 [%0], 1;" :: "r"(smb[0]));
        asm volatile("mbarrier.init.shared.b64 [%0], 1;" :: "r"(smb[1]));
    }
    __syncwarp();

    int par[2] = {0, 0};
    const int stride = gridDim.x;

    // prologue: load first chunk into stage 0
    if ((int)blockIdx.x < n_chunks && tid == 0) {
        asm volatile("mbarrier.arrive.expect_tx.shared.b64 _, [%0], %1;"
                     :: "r"(smb[0]), "r"(CHUNK_BYTES));
        asm volatile(
            "cp.async.bulk.shared::cta.global.mbarrier::complete_tx::bytes "
            "[%0], [%1], %2, [%3];"
            :: "r"(sbuf), "l"(ef + (size_t)blockIdx.x * EB * FDIM),
               "r"(CHUNK_BYTES), "r"(smb[0]) : "memory");
    }

    int it = 0;
    for (int c = blockIdx.x; c < n_chunks; c += stride, ++it) {
        const int s = it & 1;
        const unsigned mb = smb[s];
        // wait for chunk data
        {
            unsigned done;
            asm volatile(
                "{\n\t.reg .pred p;\n\t"
                "mbarrier.try_wait.parity.shared.b64 p, [%1], %2;\n\t"
                "selp.b32 %0, 1, 0, p;\n\t}"
                : "=r"(done) : "r"(mb), "r"((unsigned)par[s]) : "memory");
            while (!done) {
                asm volatile(
                    "{\n\t.reg .pred p;\n\t"
                    "mbarrier.try_wait.parity.shared.b64 p, [%1], %2, 0x98968;\n\t"
                    "selp.b32 %0, 1, 0, p;\n\t}"
                    : "=r"(done) : "r"(mb), "r"((unsigned)par[s]) : "memory");
            }
        }
        par[s] ^= 1;

        // fire reduces: one edge per lane
        {
            int e = c * EB + tid;
            int r  = __ldg(&recv[e]);
            int sn = __ldg(&send[e]);
            unsigned src = sbuf + (unsigned)(s * EB * FDIM * 4) +
                           (unsigned)(tid * FDIM * 4);
            float* d0 = &g_agg[0][(size_t)r * FDIM];
            float* d1 = &g_agg[1][(size_t)sn * FDIM];
            asm volatile(
                "cp.reduce.async.bulk.global.shared::cta.bulk_group.add.f32 "
                "[%0], [%1], 512;" :: "l"(d0), "r"(src) : "memory");
            asm volatile(
                "cp.reduce.async.bulk.global.shared::cta.bulk_group.add.f32 "
                "[%0], [%1], 512;" :: "l"(d1), "r"(src) : "memory");
            asm volatile("cp.async.bulk.commit_group;" ::: "memory");
            // drain group from 2 iterations ago -> other stage free to refill
            asm volatile("cp.async.bulk.wait_group 1;" ::: "memory");
        }
        __syncwarp();

        // prefetch next chunk into other stage
        int cn = c + stride;
        if (cn < n_chunks && tid == 0) {
            const unsigned mbo = smb[s ^ 1];
            const unsigned dst = sbuf + (unsigned)((s ^ 1) * EB * FDIM * 4);
            asm volatile("mbarrier.arrive.expect_tx.shared.b64 _, [%0], %1;"
                         :: "r"(mbo), "r"(CHUNK_BYTES));
            asm volatile(
                "cp.async.bulk.shared::cta.global.mbarrier::complete_tx::bytes "
                "[%0], [%1], %2, [%3];"
                :: "r"(dst), "l"(ef + (size_t)cn * EB * FDIM),
                   "r"(CHUNK_BYTES), "r"(mbo) : "memory");
        }
    }
    asm volatile("cp.async.bulk.wait_group 0;" ::: "memory");
}

// ---------------------------------------------------------------------------
// Fused 3-term GEMM with packed f32x2 FMA.
// Tile 128x128 (full N), BK=8, 256 threads, 8x8 per-thread blocking.
// out[m][j] = sum_ph A[ph][m][:] . W[ph][j][:]  + g_gproj[gidx[m]][j]
// ---------------------------------------------------------------------------
__global__ __launch_bounds__(256, 2) void gemm_kernel(
    const float* __restrict__ node,
    const float* __restrict__ Wn,
    const float* __restrict__ Wi,
    const float* __restrict__ Wo,
    const int* __restrict__ gidx,
    float* __restrict__ out) {
    constexpr int BM = 128, BK = 8, LDA = BM + 4;
    __shared__ __align__(16) float As[BK][LDA];
    __shared__ __align__(16) float Bs[BK][LDA];

    const int tid = threadIdx.x;
    const int tx = tid & 15;        // 8 output cols each
    const int ty = tid >> 4;        // 8 output rows each
    const int m0 = blockIdx.x * BM;
    const int lr = tid >> 1;        // load row 0..127
    const int lq = (tid & 1) * 4;   // k sub-offset 0/4

    unsigned long long acc[8][4];
#pragma unroll
    for (int i = 0; i < 8; i++)
#pragma unroll
        for (int p = 0; p < 4; p++) acc[i][p] = 0ull;

    const float* Asrc[3] = {node, g_agg[0], g_agg[1]};
    const float* Wsrc[3] = {Wn, Wi, Wo};

    const int arow = m0 + lr;
    const bool aok = (arow < N_NODES);
    const size_t aoff = (size_t)(aok ? arow : 0) * FDIM;
    const size_t woff = (size_t)lr * FDIM;

#pragma unroll 1
    for (int ph = 0; ph < 3; ph++) {
        const float* A = Asrc[ph];
        const float* W = Wsrc[ph];
#pragma unroll 1
        for (int kc = 0; kc < FDIM; kc += BK) {
            float4 a = make_float4(0.f, 0.f, 0.f, 0.f);
            if (aok) a = *(const float4*)&A[aoff + kc + lq];
            float4 b = *(const float4*)&W[woff + kc + lq];
            __syncthreads();
            As[lq + 0][lr] = a.x; As[lq + 1][lr] = a.y;
            As[lq + 2][lr] = a.z; As[lq + 3][lr] = a.w;
            Bs[lq + 0][lr] = b.x; Bs[lq + 1][lr] = b.y;
            Bs[lq + 2][lr] = b.z; Bs[lq + 3][lr] = b.w;
            __syncthreads();
#pragma unroll
            for (int k = 0; k < BK; k++) {
                const float4 a0 = *(const float4*)&As[k][ty * 8];
                const float4 a1 = *(const float4*)&As[k][ty * 8 + 4];
                const float4 b0 = *(const float4*)&Bs[k][tx * 8];
                const float4 b1 = *(const float4*)&Bs[k][tx * 8 + 4];
                unsigned long long bp0 = pk(b0.x, b0.y);
                unsigned long long bp1 = pk(b0.z, b0.w);
                unsigned long long bp2 = pk(b1.x, b1.y);
                unsigned long long bp3 = pk(b1.z, b1.w);
                const float av[8] = {a0.x, a0.y, a0.z, a0.w,
                                     a1.x, a1.y, a1.z, a1.w};
#pragma unroll
                for (int i = 0; i < 8; i++) {
                    unsigned long long ad = pk(av[i], av[i]);
                    fma2(acc[i][0], ad, bp0);
                    fma2(acc[i][1], ad, bp1);
                    fma2(acc[i][2], ad, bp2);
                    fma2(acc[i][3], ad, bp3);
                }
            }
        }
    }

    // Epilogue: + g_gproj[gidx[row]] (bias folded), float4 stores
    const int ncol = tx * 8;
#pragma unroll
    for (int i = 0; i < 8; i++) {
        int r = m0 + ty * 8 + i;
        if (r < N_NODES) {
            int g = __ldg(&gidx[r]);
            const float4 gp0 = *(const float4*)&g_gproj[(size_t)g * FDIM + ncol];
            const float4 gp1 = *(const float4*)&g_gproj[(size_t)g * FDIM + ncol + 4];
            union { unsigned long long u; float2 f; } c0, c1, c2, c3;
            c0.u = acc[i][0]; c1.u = acc[i][1];
            c2.u = acc[i][2]; c3.u = acc[i][3];
            float4 o0 = make_float4(c0.f.x + gp0.x, c0.f.y + gp0.y,
                                    c1.f.x + gp0.z, c1.f.y + gp0.w);
            float4 o1 = make_float4(c2.f.x + gp1.x, c2.f.y + gp1.y,
                                    c3.f.x + gp1.z, c3.f.y + gp1.w);
            *(float4*)&out[(size_t)r * FDIM + ncol] = o0;
            *(float4*)&out[(size_t)r * FDIM + ncol + 4] = o1;
        }
    }
}

// ---------------------------------------------------------------------------
// Launch
// ---------------------------------------------------------------------------
extern "C" void kernel_launch(void* const* d_in, const int* in_sizes, int n_in,
                              void* d_out, int out_size) {
    const float* node_features   = (const float*)d_in[0];
    const float* edge_features   = (const float*)d_in[1];
    const float* global_features = (const float*)d_in[2];
    const float* W_node     = (const float*)d_in[3];
    const float* W_incoming = (const float*)d_in[4];
    const float* W_outgoing = (const float*)d_in[5];
    const float* W_global   = (const float*)d_in[6];
    const float* bias       = (const float*)d_in[7];
    const int*   receivers  = (const int*)d_in[8];
    const int*   senders    = (const int*)d_in[9];
    const int*   graph_idx  = (const int*)d_in[10];
    float* out = (float*)d_out;

    zero_kernel<<<1024, 256>>>();
    gproj_kernel<<<N_GRAPHS, FDIM>>>(global_features, W_global, bias);

    {
        int n_chunks = N_EDGES / EB;           // 50000
        int grid = 148 * 6;                    // 6 blocks/SM by smem
        scatter_kernel<<<grid, 32>>>(edge_features, receivers, senders,
                                     n_chunks);
    }
    {
        dim3 grid((N_NODES + 127) / 128, 1);
        gemm_kernel<<<grid, 256>>>(node_features, W_node, W_incoming,
                                   W_outgoing, graph_idx, out);
    }
}

// round 4
// speedup vs baseline: 1.7119x; 1.7119x over previous
#include <cuda_runtime.h>
#include <cuda_bf16.h>
#include <cstdint>

#define N_NODES  100000
#define N_EDGES  1600000
#define N_GRAPHS 50
#define FDIM     128

// Scratch
__device__ __align__(128) float g_agg[2][(size_t)N_NODES * FDIM];
__device__ __align__(128) float g_gproj[N_GRAPHS * FDIM];
__device__ __align__(128) __nv_bfloat16 g_Whi[3 * FDIM * FDIM];
__device__ __align__(128) __nv_bfloat16 g_Wlo[3 * FDIM * FDIM];

// ---------------------------------------------------------------------------
// helpers
// ---------------------------------------------------------------------------
__device__ __forceinline__ unsigned smem_u32(const void* p) {
    unsigned a;
    asm("{ .reg .u64 t; cvta.to.shared.u64 t, %1; cvt.u32.u64 %0, t; }"
        : "=r"(a) : "l"(p));
    return a;
}
// pack residuals: element0 -> low half
__device__ __forceinline__ unsigned pbf2(float lo, float hi) {
    unsigned r;
    asm("cvt.rn.bf16x2.f32 %0, %1, %2;" : "=r"(r) : "f"(hi), "f"(lo));
    return r;
}
__device__ __forceinline__ void ldsm4(unsigned* r, unsigned addr) {
    asm volatile("ldmatrix.sync.aligned.m8n8.x4.shared.b16 {%0,%1,%2,%3}, [%4];"
                 : "=r"(r[0]), "=r"(r[1]), "=r"(r[2]), "=r"(r[3]) : "r"(addr));
}
__device__ __forceinline__ void mma_bf16(float* c, const unsigned* a,
                                         const unsigned* b) {
    asm volatile(
        "mma.sync.aligned.m16n8k16.row.col.f32.bf16.bf16.f32 "
        "{%0,%1,%2,%3}, {%4,%5,%6,%7}, {%8,%9}, {%0,%1,%2,%3};"
        : "+f"(c[0]), "+f"(c[1]), "+f"(c[2]), "+f"(c[3])
        : "r"(a[0]), "r"(a[1]), "r"(a[2]), "r"(a[3]), "r"(b[0]), "r"(b[1]));
}

// ---------------------------------------------------------------------------
// Zero the aggregation buffers
// ---------------------------------------------------------------------------
__global__ void zero_kernel() {
    size_t n = ((size_t)2 * N_NODES * FDIM) / 4;
    float4* p = (float4*)g_agg;
    float4 z = make_float4(0.f, 0.f, 0.f, 0.f);
    for (size_t i = (size_t)blockIdx.x * blockDim.x + threadIdx.x; i < n;
         i += (size_t)gridDim.x * blockDim.x)
        p[i] = z;
}

// ---------------------------------------------------------------------------
// Split weights into bf16 hi/lo
// ---------------------------------------------------------------------------
__global__ void wsplit_kernel(const float* __restrict__ Wn,
                              const float* __restrict__ Wi,
                              const float* __restrict__ Wo) {
    int i = blockIdx.x * blockDim.x + threadIdx.x;
    if (i >= 3 * FDIM * FDIM) return;
    const float* W[3] = {Wn, Wi, Wo};
    float w = W[i >> 14][i & 16383];
    __nv_bfloat16 h = __float2bfloat16_rn(w);
    g_Whi[i] = h;
    g_Wlo[i] = __float2bfloat16_rn(w - __bfloat162float(h));
}

// ---------------------------------------------------------------------------
// Project globals: g_gproj[g][j] = dot(G[g], Wg[j]) + bias[j]  (fp32 exact)
// ---------------------------------------------------------------------------
__global__ void gproj_kernel(const float* __restrict__ gf,
                             const float* __restrict__ Wg,
                             const float* __restrict__ bias) {
    __shared__ float s[FDIM];
    int g = blockIdx.x, j = threadIdx.x;
    s[j] = gf[g * FDIM + j];
    __syncthreads();
    const float4* wrow = (const float4*)(Wg + (size_t)j * FDIM);
    float acc = 0.f;
#pragma unroll
    for (int k = 0; k < FDIM / 4; k++) {
        float4 w = wrow[k];
        const float4 a = *(const float4*)&s[k * 4];
        acc += a.x * w.x + a.y * w.y + a.z * w.z + a.w * w.w;
    }
    g_gproj[g * FDIM + j] = acc + bias[j];
}

// ---------------------------------------------------------------------------
// Scatter-add (R1, REDG lane-rate bound): warp per edge, red.v4.f32
// ---------------------------------------------------------------------------
__global__ void scatter_kernel(const float4* __restrict__ ef,
                               const int* __restrict__ recv,
                               const int* __restrict__ send) {
    int w = (int)((blockIdx.x * (size_t)blockDim.x + threadIdx.x) >> 5);
    int lane = threadIdx.x & 31;
    if (w >= N_EDGES) return;
    float4 v = __ldg(&ef[(size_t)w * (FDIM / 4) + lane]);
    int r = __ldg(&recv[w]);
    int s = __ldg(&send[w]);
    float* pr = &g_agg[0][(size_t)r * FDIM + lane * 4];
    float* ps = &g_agg[1][(size_t)s * FDIM + lane * 4];
    asm volatile("red.global.add.v4.f32 [%0], {%1,%2,%3,%4};"
                 :: "l"(pr), "f"(v.x), "f"(v.y), "f"(v.z), "f"(v.w) : "memory");
    asm volatile("red.global.add.v4.f32 [%0], {%1,%2,%3,%4};"
                 :: "l"(ps), "f"(v.x), "f"(v.y), "f"(v.z), "f"(v.w) : "memory");
}

// ---------------------------------------------------------------------------
// mma.sync bf16 split-3 GEMM.
// Tile: BM=128, BN=128 (full), BK=32, 256 threads (8 warps: 4m x 2n).
// smem: operands stored as contiguous 8x8 b16 tiles (128B) -> conflict-free
// ldmatrix.x4. D = Ah*Bh + Ah*Bl + Al*Bh (+ gproj[gidx] epilogue).
// ---------------------------------------------------------------------------
// tile offset: row r, k element index kk (within 32-wide chunk)
#define TOFF(r, kk) (((r) >> 3) * 512 + ((kk) >> 3) * 128 + ((r)&7) * 16 + ((kk)&7) * 2)

__global__ __launch_bounds__(256, 1) void gemm_kernel(
    const float* __restrict__ node,
    const int* __restrict__ gidx,
    float* __restrict__ out) {
    // regions: Ah | Al | Bh | Bl, each 128x32 bf16 = 8KB
    __shared__ __align__(128) unsigned char sm[4 * 8192];
    const unsigned sA = smem_u32(sm);

    const int tid = threadIdx.x;
    const int wid = tid >> 5, lid = tid & 31;
    const int wm = wid & 3, wn = wid >> 2;
    const int m0 = blockIdx.x * 128;

    // ldmatrix lane addressing
    const int t8 = lid >> 3, r8 = lid & 7;
    // A frag tiles: t -> (m_off = (t&1)*8, k_off = (t>>1)*8)
    const unsigned aOff = (unsigned)TOFF(wm * 32 + (t8 & 1) * 8 + r8, (t8 >> 1) * 8);
    // B pair tiles: t -> (n_off = (t>>1)*8, k_off = (t&1)*8)
    const unsigned bOff = (unsigned)TOFF(wn * 64 + (t8 >> 1) * 8 + r8, (t8 & 1) * 8);

    const unsigned aHi = sA + aOff;            // +1024 for mt=1, +8192 for lo
    const unsigned bHi = sA + 16384 + bOff;    // +1024 per np,  +8192 for lo

    float acc[2][8][4];
#pragma unroll
    for (int i = 0; i < 2; i++)
#pragma unroll
        for (int j = 0; j < 8; j++)
#pragma unroll
            for (int q = 0; q < 4; q++) acc[i][j][q] = 0.f;

    const float* Asrc[3] = {node, g_agg[0], g_agg[1]};

    // fill-side indices: thread -> (row, k-half)
    const int frow = tid >> 1;
    const int fkh = (tid & 1) * 16;
    int arow_g = m0 + frow;
    if (arow_g >= N_NODES) arow_g = N_NODES - 1;  // clamp (stores guarded)

#pragma unroll 1
    for (int ch = 0; ch < 12; ch++) {
        const int p = ch >> 2;
        const int kc = (ch & 3) * 32;

        __syncthreads();
        // ---- fill A: fp32 -> bf16 hi/lo ----
        {
            const float* ap = Asrc[p] + (size_t)arow_g * FDIM + kc + fkh;
#pragma unroll
            for (int g = 0; g < 2; g++) {
                float4 f0 = *(const float4*)(ap + g * 8);
                float4 f1 = *(const float4*)(ap + g * 8 + 4);
                __nv_bfloat16 h0 = __float2bfloat16_rn(f0.x);
                __nv_bfloat16 h1 = __float2bfloat16_rn(f0.y);
                __nv_bfloat16 h2 = __float2bfloat16_rn(f0.z);
                __nv_bfloat16 h3 = __float2bfloat16_rn(f0.w);
                __nv_bfloat16 h4 = __float2bfloat16_rn(f1.x);
                __nv_bfloat16 h5 = __float2bfloat16_rn(f1.y);
                __nv_bfloat16 h6 = __float2bfloat16_rn(f1.z);
                __nv_bfloat16 h7 = __float2bfloat16_rn(f1.w);
                uint4 vh;
                vh.x = ((unsigned)__bfloat16_as_ushort(h1) << 16) | __bfloat16_as_ushort(h0);
                vh.y = ((unsigned)__bfloat16_as_ushort(h3) << 16) | __bfloat16_as_ushort(h2);
                vh.z = ((unsigned)__bfloat16_as_ushort(h5) << 16) | __bfloat16_as_ushort(h4);
                vh.w = ((unsigned)__bfloat16_as_ushort(h7) << 16) | __bfloat16_as_ushort(h6);
                uint4 vl;
                vl.x = pbf2(f0.x - __bfloat162float(h0), f0.y - __bfloat162float(h1));
                vl.y = pbf2(f0.z - __bfloat162float(h2), f0.w - __bfloat162float(h3));
                vl.z = pbf2(f1.x - __bfloat162float(h4), f1.y - __bfloat162float(h5));
                vl.w = pbf2(f1.z - __bfloat162float(h6), f1.w - __bfloat162float(h7));
                unsigned off = (unsigned)((frow >> 3) * 512 + ((fkh >> 3) + g) * 128 +
                                          (frow & 7) * 16);
                *(uint4*)(sm + off) = vh;
                *(uint4*)(sm + 8192 + off) = vl;
            }
        }
        // ---- fill B: precomputed bf16 hi/lo ----
        {
            const unsigned char* bh = (const unsigned char*)g_Whi +
                ((size_t)p * FDIM * FDIM + (size_t)frow * FDIM + kc + fkh) * 2;
            const unsigned char* bl = (const unsigned char*)g_Wlo +
                ((size_t)p * FDIM * FDIM + (size_t)frow * FDIM + kc + fkh) * 2;
#pragma unroll
            for (int g = 0; g < 2; g++) {
                uint4 vh = *(const uint4*)(bh + g * 16);
                uint4 vl = *(const uint4*)(bl + g * 16);
                unsigned off = (unsigned)((frow >> 3) * 512 + ((fkh >> 3) + g) * 128 +
                                          (frow & 7) * 16);
                *(uint4*)(sm + 16384 + off) = vh;
                *(uint4*)(sm + 24576 + off) = vl;
            }
        }
        __syncthreads();

        // ---- MMA over BK=32 (two k16 steps) ----
#pragma unroll
        for (int ks = 0; ks < 2; ks++) {
            const unsigned kso = ks * 256;
            unsigned ah[2][4], al[2][4];
            ldsm4(ah[0], aHi + kso);
            ldsm4(ah[1], aHi + 1024 + kso);
            ldsm4(al[0], aHi + 8192 + kso);
            ldsm4(al[1], aHi + 9216 + kso);
#pragma unroll
            for (int np = 0; np < 4; np++) {
                unsigned bh[4], bl[4];
                ldsm4(bh, bHi + np * 1024 + kso);
                ldsm4(bl, bHi + 8192 + np * 1024 + kso);
#pragma unroll
                for (int mt = 0; mt < 2; mt++) {
                    mma_bf16(acc[mt][np * 2], ah[mt], bh);
                    mma_bf16(acc[mt][np * 2 + 1], ah[mt], bh + 2);
                    mma_bf16(acc[mt][np * 2], ah[mt], bl);
                    mma_bf16(acc[mt][np * 2 + 1], ah[mt], bl + 2);
                    mma_bf16(acc[mt][np * 2], al[mt], bh);
                    mma_bf16(acc[mt][np * 2 + 1], al[mt], bh + 2);
                }
            }
        }
    }

    // ---- epilogue: + gproj[gidx[row]] ----
    const int quad = lid >> 2, qlane = lid & 3;
#pragma unroll
    for (int mt = 0; mt < 2; mt++) {
        const int r0 = m0 + wm * 32 + mt * 16 + quad;
        const int r1 = r0 + 8;
        const bool ok0 = r0 < N_NODES, ok1 = r1 < N_NODES;
        const float* gp0 = g_gproj + (size_t)(ok0 ? __ldg(&gidx[r0]) : 0) * FDIM;
        const float* gp1 = g_gproj + (size_t)(ok1 ? __ldg(&gidx[r1]) : 0) * FDIM;
#pragma unroll
        for (int nt = 0; nt < 8; nt++) {
            const int col = wn * 64 + nt * 8 + qlane * 2;
            if (ok0) {
                float2 g0 = *(const float2*)(gp0 + col);
                float2 o0 = make_float2(acc[mt][nt][0] + g0.x, acc[mt][nt][1] + g0.y);
                *(float2*)(out + (size_t)r0 * FDIM + col) = o0;
            }
            if (ok1) {
                float2 g1 = *(const float2*)(gp1 + col);
                float2 o1 = make_float2(acc[mt][nt][2] + g1.x, acc[mt][nt][3] + g1.y);
                *(float2*)(out + (size_t)r1 * FDIM + col) = o1;
            }
        }
    }
}

// ---------------------------------------------------------------------------
// Launch
// ---------------------------------------------------------------------------
extern "C" void kernel_launch(void* const* d_in, const int* in_sizes, int n_in,
                              void* d_out, int out_size) {
    const float* node_features   = (const float*)d_in[0];
    const float* edge_features   = (const float*)d_in[1];
    const float* global_features = (const float*)d_in[2];
    const float* W_node     = (const float*)d_in[3];
    const float* W_incoming = (const float*)d_in[4];
    const float* W_outgoing = (const float*)d_in[5];
    const float* W_global   = (const float*)d_in[6];
    const float* bias       = (const float*)d_in[7];
    const int*   receivers  = (const int*)d_in[8];
    const int*   senders    = (const int*)d_in[9];
    const int*   graph_idx  = (const int*)d_in[10];
    float* out = (float*)d_out;

    zero_kernel<<<1024, 256>>>();
    wsplit_kernel<<<(3 * FDIM * FDIM + 255) / 256, 256>>>(W_node, W_incoming,
                                                          W_outgoing);
    gproj_kernel<<<N_GRAPHS, FDIM>>>(global_features, W_global, bias);

    {
        int threads = 256;
        long long total = (long long)N_EDGES * 32;
        int blocks = (int)((total + threads - 1) / threads);
        scatter_kernel<<<blocks, threads>>>((const float4*)edge_features,
                                            receivers, senders);
    }
    {
        int grid = (N_NODES + 127) / 128;  // 782
        gemm_kernel<<<grid, 256>>>(node_features, graph_idx, out);
    }
}

// round 7
// speedup vs baseline: 1.9566x; 1.1429x over previous
#include <cuda_runtime.h>
#include <cuda_bf16.h>
#include <cstdint>

#define N_NODES  100000
#define N_EDGES  1600000
#define N_GRAPHS 50
#define FDIM     128

// Scratch
__device__ __align__(128) float g_agg[2][(size_t)N_NODES * FDIM];
__device__ __align__(128) float g_gproj[N_GRAPHS * FDIM];
__device__ __align__(128) __nv_bfloat16 g_Whi[3 * FDIM * FDIM];
__device__ __align__(128) __nv_bfloat16 g_Wlo[3 * FDIM * FDIM];

// ---------------------------------------------------------------------------
// helpers
// ---------------------------------------------------------------------------
__device__ __forceinline__ unsigned smem_u32(const void* p) {
    unsigned a;
    asm("{ .reg .u64 t; cvta.to.shared.u64 t, %1; cvt.u32.u64 %0, t; }"
        : "=r"(a) : "l"(p));
    return a;
}
// pack residuals: element0 -> low half
__device__ __forceinline__ unsigned pbf2(float lo, float hi) {
    unsigned r;
    asm("cvt.rn.bf16x2.f32 %0, %1, %2;" : "=r"(r) : "f"(hi), "f"(lo));
    return r;
}
__device__ __forceinline__ void ldsm4(unsigned* r, unsigned addr) {
    asm volatile("ldmatrix.sync.aligned.m8n8.x4.shared.b16 {%0,%1,%2,%3}, [%4];"
                 : "=r"(r[0]), "=r"(r[1]), "=r"(r[2]), "=r"(r[3]) : "r"(addr));
}
__device__ __forceinline__ void mma_bf16(float* c, const unsigned* a,
                                         const unsigned* b) {
    asm volatile(
        "mma.sync.aligned.m16n8k16.row.col.f32.bf16.bf16.f32 "
        "{%0,%1,%2,%3}, {%4,%5,%6,%7}, {%8,%9}, {%0,%1,%2,%3};"
        : "+f"(c[0]), "+f"(c[1]), "+f"(c[2]), "+f"(c[3])
        : "r"(a[0]), "r"(a[1]), "r"(a[2]), "r"(a[3]), "r"(b[0]), "r"(b[1]));
}

// ---------------------------------------------------------------------------
// Zero the aggregation buffers
// ---------------------------------------------------------------------------
__global__ void zero_kernel() {
    size_t n = ((size_t)2 * N_NODES * FDIM) / 4;
    float4* p = (float4*)g_agg;
    float4 z = make_float4(0.f, 0.f, 0.f, 0.f);
    for (size_t i = (size_t)blockIdx.x * blockDim.x + threadIdx.x; i < n;
         i += (size_t)gridDim.x * blockDim.x)
        p[i] = z;
}

// ---------------------------------------------------------------------------
// Split weights into bf16 hi/lo
// ---------------------------------------------------------------------------
__global__ void wsplit_kernel(const float* __restrict__ Wn,
                              const float* __restrict__ Wi,
                              const float* __restrict__ Wo) {
    int i = blockIdx.x * blockDim.x + threadIdx.x;
    if (i >= 3 * FDIM * FDIM) return;
    const float* W[3] = {Wn, Wi, Wo};
    float w = W[i >> 14][i & 16383];
    __nv_bfloat16 h = __float2bfloat16_rn(w);
    g_Whi[i] = h;
    g_Wlo[i] = __float2bfloat16_rn(w - __bfloat162float(h));
}

// ---------------------------------------------------------------------------
// Project globals: g_gproj[g][j] = dot(G[g], Wg[j]) + bias[j]  (fp32 exact)
// ---------------------------------------------------------------------------
__global__ void gproj_kernel(const float* __restrict__ gf,
                             const float* __restrict__ Wg,
                             const float* __restrict__ bias) {
    __shared__ float s[FDIM];
    int g = blockIdx.x, j = threadIdx.x;
    s[j] = gf[g * FDIM + j];
    __syncthreads();
    const float4* wrow = (const float4*)(Wg + (size_t)j * FDIM);
    float acc = 0.f;
#pragma unroll
    for (int k = 0; k < FDIM / 4; k++) {
        float4 w = wrow[k];
        const float4 a = *(const float4*)&s[k * 4];
        acc += a.x * w.x + a.y * w.y + a.z * w.z + a.w * w.w;
    }
    g_gproj[g * FDIM + j] = acc + bias[j];
}

// ---------------------------------------------------------------------------
// Scatter-add: warp per edge, red.v4.f32.
// Edge stream: cache-hint policy evict_first (don't displace accumulators).
// Reductions: cache-hint policy evict_last (pin the 102MB agg set in L2).
// ---------------------------------------------------------------------------
__global__ void scatter_kernel(const float4* __restrict__ ef,
                               const int* __restrict__ recv,
                               const int* __restrict__ send) {
    int w = (int)((blockIdx.x * (size_t)blockDim.x + threadIdx.x) >> 5);
    int lane = threadIdx.x & 31;
    if (w >= N_EDGES) return;

    unsigned long long pol_last, pol_first;
    asm("createpolicy.fractional.L2::evict_last.b64 %0, 1.0;" : "=l"(pol_last));
    asm("createpolicy.fractional.L2::evict_first.b64 %0, 1.0;" : "=l"(pol_first));

    float4 v;
    asm volatile("ld.global.nc.L2::cache_hint.v4.f32 {%0,%1,%2,%3}, [%4], %5;"
                 : "=f"(v.x), "=f"(v.y), "=f"(v.z), "=f"(v.w)
                 : "l"(&ef[(size_t)w * (FDIM / 4) + lane]), "l"(pol_first));
    int r = __ldg(&recv[w]);
    int s = __ldg(&send[w]);
    float* pr = &g_agg[0][(size_t)r * FDIM + lane * 4];
    float* ps = &g_agg[1][(size_t)s * FDIM + lane * 4];
    asm volatile("red.global.add.L2::cache_hint.v4.f32 [%0], {%1,%2,%3,%4}, %5;"
                 :: "l"(pr), "f"(v.x), "f"(v.y), "f"(v.z), "f"(v.w), "l"(pol_last)
                 : "memory");
    asm volatile("red.global.add.L2::cache_hint.v4.f32 [%0], {%1,%2,%3,%4}, %5;"
                 :: "l"(ps), "f"(v.x), "f"(v.y), "f"(v.z), "f"(v.w), "l"(pol_last)
                 : "memory");
}

// ---------------------------------------------------------------------------
// mma.sync bf16 split-3 GEMM (unchanged from R4 WIN).
// Tile: BM=128, BN=128, BK=32, 256 threads (8 warps: 4m x 2n).
// ---------------------------------------------------------------------------
#define TOFF(r, kk) (((r) >> 3) * 512 + ((kk) >> 3) * 128 + ((r)&7) * 16 + ((kk)&7) * 2)

__global__ __launch_bounds__(256, 1) void gemm_kernel(
    const float* __restrict__ node,
    const int* __restrict__ gidx,
    float* __restrict__ out) {
    __shared__ __align__(128) unsigned char sm[4 * 8192];
    const unsigned sA = smem_u32(sm);

    const int tid = threadIdx.x;
    const int wid = tid >> 5, lid = tid & 31;
    const int wm = wid & 3, wn = wid >> 2;
    const int m0 = blockIdx.x * 128;

    const int t8 = lid >> 3, r8 = lid & 7;
    const unsigned aOff = (unsigned)TOFF(wm * 32 + (t8 & 1) * 8 + r8, (t8 >> 1) * 8);
    const unsigned bOff = (unsigned)TOFF(wn * 64 + (t8 >> 1) * 8 + r8, (t8 & 1) * 8);

    const unsigned aHi = sA + aOff;
    const unsigned bHi = sA + 16384 + bOff;

    float acc[2][8][4];
#pragma unroll
    for (int i = 0; i < 2; i++)
#pragma unroll
        for (int j = 0; j < 8; j++)
#pragma unroll
            for (int q = 0; q < 4; q++) acc[i][j][q] = 0.f;

    const float* Asrc[3] = {node, g_agg[0], g_agg[1]};

    const int frow = tid >> 1;
    const int fkh = (tid & 1) * 16;
    int arow_g = m0 + frow;
    if (arow_g >= N_NODES) arow_g = N_NODES - 1;

#pragma unroll 1
    for (int ch = 0; ch < 12; ch++) {
        const int p = ch >> 2;
        const int kc = (ch & 3) * 32;

        __syncthreads();
        {
            const float* ap = Asrc[p] + (size_t)arow_g * FDIM + kc + fkh;
#pragma unroll
            for (int g = 0; g < 2; g++) {
                float4 f0 = *(const float4*)(ap + g * 8);
                float4 f1 = *(const float4*)(ap + g * 8 + 4);
                __nv_bfloat16 h0 = __float2bfloat16_rn(f0.x);
                __nv_bfloat16 h1 = __float2bfloat16_rn(f0.y);
                __nv_bfloat16 h2 = __float2bfloat16_rn(f0.z);
                __nv_bfloat16 h3 = __float2bfloat16_rn(f0.w);
                __nv_bfloat16 h4 = __float2bfloat16_rn(f1.x);
                __nv_bfloat16 h5 = __float2bfloat16_rn(f1.y);
                __nv_bfloat16 h6 = __float2bfloat16_rn(f1.z);
                __nv_bfloat16 h7 = __float2bfloat16_rn(f1.w);
                uint4 vh;
                vh.x = ((unsigned)__bfloat16_as_ushort(h1) << 16) | __bfloat16_as_ushort(h0);
                vh.y = ((unsigned)__bfloat16_as_ushort(h3) << 16) | __bfloat16_as_ushort(h2);
                vh.z = ((unsigned)__bfloat16_as_ushort(h5) << 16) | __bfloat16_as_ushort(h4);
                vh.w = ((unsigned)__bfloat16_as_ushort(h7) << 16) | __bfloat16_as_ushort(h6);
                uint4 vl;
                vl.x = pbf2(f0.x - __bfloat162float(h0), f0.y - __bfloat162float(h1));
                vl.y = pbf2(f0.z - __bfloat162float(h2), f0.w - __bfloat162float(h3));
                vl.z = pbf2(f1.x - __bfloat162float(h4), f1.y - __bfloat162float(h5));
                vl.w = pbf2(f1.z - __bfloat162float(h6), f1.w - __bfloat162float(h7));
                unsigned off = (unsigned)((frow >> 3) * 512 + ((fkh >> 3) + g) * 128 +
                                          (frow & 7) * 16);
                *(uint4*)(sm + off) = vh;
                *(uint4*)(sm + 8192 + off) = vl;
            }
        }
        {
            const unsigned char* bh = (const unsigned char*)g_Whi +
                ((size_t)p * FDIM * FDIM + (size_t)frow * FDIM + kc + fkh) * 2;
            const unsigned char* bl = (const unsigned char*)g_Wlo +
                ((size_t)p * FDIM * FDIM + (size_t)frow * FDIM + kc + fkh) * 2;
#pragma unroll
            for (int g = 0; g < 2; g++) {
                uint4 vh = *(const uint4*)(bh + g * 16);
                uint4 vl = *(const uint4*)(bl + g * 16);
                unsigned off = (unsigned)((frow >> 3) * 512 + ((fkh >> 3) + g) * 128 +
                                          (frow & 7) * 16);
                *(uint4*)(sm + 16384 + off) = vh;
                *(uint4*)(sm + 24576 + off) = vl;
            }
        }
        __syncthreads();

#pragma unroll
        for (int ks = 0; ks < 2; ks++) {
            const unsigned kso = ks * 256;
            unsigned ah[2][4], al[2][4];
            ldsm4(ah[0], aHi + kso);
            ldsm4(ah[1], aHi + 1024 + kso);
            ldsm4(al[0], aHi + 8192 + kso);
            ldsm4(al[1], aHi + 9216 + kso);
#pragma unroll
            for (int np = 0; np < 4; np++) {
                unsigned bh[4], bl[4];
                ldsm4(bh, bHi + np * 1024 + kso);
                ldsm4(bl, bHi + 8192 + np * 1024 + kso);
#pragma unroll
                for (int mt = 0; mt < 2; mt++) {
                    mma_bf16(acc[mt][np * 2], ah[mt], bh);
                    mma_bf16(acc[mt][np * 2 + 1], ah[mt], bh + 2);
                    mma_bf16(acc[mt][np * 2], ah[mt], bl);
                    mma_bf16(acc[mt][np * 2 + 1], ah[mt], bl + 2);
                    mma_bf16(acc[mt][np * 2], al[mt], bh);
                    mma_bf16(acc[mt][np * 2 + 1], al[mt], bh + 2);
                }
            }
        }
    }

    const int quad = lid >> 2, qlane = lid & 3;
#pragma unroll
    for (int mt = 0; mt < 2; mt++) {
        const int r0 = m0 + wm * 32 + mt * 16 + quad;
        const int r1 = r0 + 8;
        const bool ok0 = r0 < N_NODES, ok1 = r1 < N_NODES;
        const float* gp0 = g_gproj + (size_t)(ok0 ? __ldg(&gidx[r0]) : 0) * FDIM;
        const float* gp1 = g_gproj + (size_t)(ok1 ? __ldg(&gidx[r1]) : 0) * FDIM;
#pragma unroll
        for (int nt = 0; nt < 8; nt++) {
            const int col = wn * 64 + nt * 8 + qlane * 2;
            if (ok0) {
                float2 g0 = *(const float2*)(gp0 + col);
                float2 o0 = make_float2(acc[mt][nt][0] + g0.x, acc[mt][nt][1] + g0.y);
                *(float2*)(out + (size_t)r0 * FDIM + col) = o0;
            }
            if (ok1) {
                float2 g1 = *(const float2*)(gp1 + col);
                float2 o1 = make_float2(acc[mt][nt][2] + g1.x, acc[mt][nt][3] + g1.y);
                *(float2*)(out + (size_t)r1 * FDIM + col) = o1;
            }
        }
    }
}

// ---------------------------------------------------------------------------
// Launch
// ---------------------------------------------------------------------------
extern "C" void kernel_launch(void* const* d_in, const int* in_sizes, int n_in,
                              void* d_out, int out_size) {
    const float* node_features   = (const float*)d_in[0];
    const float* edge_features   = (const float*)d_in[1];
    const float* global_features = (const float*)d_in[2];
    const float* W_node     = (const float*)d_in[3];
    const float* W_incoming = (const float*)d_in[4];
    const float* W_outgoing = (const float*)d_in[5];
    const float* W_global   = (const float*)d_in[6];
    const float* bias       = (const float*)d_in[7];
    const int*   receivers  = (const int*)d_in[8];
    const int*   senders    = (const int*)d_in[9];
    const int*   graph_idx  = (const int*)d_in[10];
    float* out = (float*)d_out;

    zero_kernel<<<1024, 256>>>();
    wsplit_kernel<<<(3 * FDIM * FDIM + 255) / 256, 256>>>(W_node, W_incoming,
                                                          W_outgoing);
    gproj_kernel<<<N_GRAPHS, FDIM>>>(global_features, W_global, bias);

    {
        int threads = 256;
        long long total = (long long)N_EDGES * 32;
        int blocks = (int)((total + threads - 1) / threads);
        scatter_kernel<<<blocks, threads>>>((const float4*)edge_features,
                                            receivers, senders);
    }
    {
        int grid = (N_NODES + 127) / 128;  // 782
        gemm_kernel<<<grid, 256>>>(node_features, graph_idx, out);
    }
}